// round 1
// baseline (speedup 1.0000x reference)
#include <cuda_runtime.h>
#include <math.h>

// ---------------- problem constants ----------------
#define B_   2
#define S_   2048
#define H_   1024
#define NH_  16
#define HD_  64
#define T_   (B_*S_)      // 4096 tokens
#define FFN_ 4096
#define ROT_ 16

// ---------------- static scratch (no allocs allowed) ----------------
__device__ float d_xn [T_*H_];
__device__ float d_big[T_*FFN_];   // slot activations (qkv/proj use first T_*1024)
__device__ float d_q  [T_*H_];
__device__ float d_k  [T_*H_];
__device__ float d_v  [T_*H_];
__device__ float d_o  [T_*H_];
__device__ float d_x1 [T_*H_];
__device__ float d_tmp[T_*H_];

// ---------------- helpers ----------------
__device__ __forceinline__ float gelu_exact(float x) {
    return 0.5f * x * (1.0f + erff(x * 0.7071067811865475f));
}

__device__ __forceinline__ float block_reduce_sum(float v, float* sh) {
    int lane = threadIdx.x & 31, wid = threadIdx.x >> 5;
    #pragma unroll
    for (int o = 16; o > 0; o >>= 1) v += __shfl_down_sync(0xffffffffu, v, o);
    if (lane == 0) sh[wid] = v;
    __syncthreads();
    float r = (threadIdx.x < (blockDim.x >> 5)) ? sh[threadIdx.x] : 0.0f;
    if (wid == 0) {
        #pragma unroll
        for (int o = 4; o > 0; o >>= 1) r += __shfl_down_sync(0xffffffffu, r, o);
        if (lane == 0) sh[0] = r;
    }
    __syncthreads();
    r = sh[0];
    __syncthreads();
    return r;
}

// ---------------- LayerNorm: one block per token, H=1024 ----------------
__global__ void ln_kernel(const float* __restrict__ x, const float* __restrict__ w,
                          const float* __restrict__ b, float* __restrict__ y) {
    __shared__ float sh[32];
    int row = blockIdx.x;
    int tid = threadIdx.x;
    const float4 v = *(const float4*)(x + (size_t)row * H_ + tid * 4);
    float s  = v.x + v.y + v.z + v.w;
    float sq = v.x*v.x + v.y*v.y + v.z*v.z + v.w*v.w;
    float S  = block_reduce_sum(s,  sh);
    float SQ = block_reduce_sum(sq, sh);
    float mu  = S * (1.0f / H_);
    float var = SQ * (1.0f / H_) - mu * mu;
    float inv = rsqrtf(var + 1e-5f);
    const float4 wv = *(const float4*)(w + tid * 4);
    const float4 bv = *(const float4*)(b + tid * 4);
    float4 o;
    o.x = (v.x - mu) * inv * wv.x + bv.x;
    o.y = (v.y - mu) * inv * wv.y + bv.y;
    o.z = (v.z - mu) * inv * wv.z + bv.z;
    o.w = (v.w - mu) * inv * wv.w + bv.w;
    *(float4*)(y + (size_t)row * H_ + tid * 4) = o;
}

// ---------------- SGEMM 128x128x16, 8x8 per thread ----------------
// C[M,N] = alpha * A[M,K] @ op(B);  TB: B is [N,K] (NT), else B is [K,N] (NN)
template <bool TB>
__global__ void __launch_bounds__(256) sgemm_kernel(
    const float* __restrict__ A, const float* __restrict__ Bm, float* __restrict__ C,
    int M, int N, int K, float alpha)
{
    __shared__ float As[16][132];
    __shared__ float Bs[16][132];
    const int bx = blockIdx.x, by = blockIdx.y;
    const int tid = threadIdx.x, tx = tid & 15, ty = tid >> 4;
    float acc[8][8];
    #pragma unroll
    for (int i = 0; i < 8; i++)
        #pragma unroll
        for (int j = 0; j < 8; j++) acc[i][j] = 0.0f;

    const float* Ab = A + (size_t)by * 128 * K;

    for (int k0 = 0; k0 < K; k0 += 16) {
        // A tile: [128 rows][16 cols] -> As[k][m]
        {
            int r = tid >> 2, c4 = tid & 3;
            #pragma unroll
            for (int it = 0; it < 2; it++) {
                int rr = r + it * 64;
                const float4 v = *(const float4*)(Ab + (size_t)rr * K + k0 + c4 * 4);
                As[c4*4+0][rr] = v.x;
                As[c4*4+1][rr] = v.y;
                As[c4*4+2][rr] = v.z;
                As[c4*4+3][rr] = v.w;
            }
        }
        if (TB) {
            const float* Bb = Bm + (size_t)bx * 128 * K;
            int r = tid >> 2, c4 = tid & 3;
            #pragma unroll
            for (int it = 0; it < 2; it++) {
                int rr = r + it * 64;
                const float4 v = *(const float4*)(Bb + (size_t)rr * K + k0 + c4 * 4);
                Bs[c4*4+0][rr] = v.x;
                Bs[c4*4+1][rr] = v.y;
                Bs[c4*4+2][rr] = v.z;
                Bs[c4*4+3][rr] = v.w;
            }
        } else {
            int r = tid >> 5, c4 = tid & 31;
            #pragma unroll
            for (int it = 0; it < 2; it++) {
                int rr = r + it * 8;
                const float4 v = *(const float4*)(Bm + (size_t)(k0 + rr) * N + bx * 128 + c4 * 4);
                *(float4*)&Bs[rr][c4 * 4] = v;
            }
        }
        __syncthreads();

        #pragma unroll
        for (int k = 0; k < 16; k++) {
            float4 a0 = *(const float4*)&As[k][ty * 8];
            float4 a1 = *(const float4*)&As[k][ty * 8 + 4];
            float4 b0 = *(const float4*)&Bs[k][tx * 8];
            float4 b1 = *(const float4*)&Bs[k][tx * 8 + 4];
            float a[8] = {a0.x, a0.y, a0.z, a0.w, a1.x, a1.y, a1.z, a1.w};
            float bb[8] = {b0.x, b0.y, b0.z, b0.w, b1.x, b1.y, b1.z, b1.w};
            #pragma unroll
            for (int i = 0; i < 8; i++)
                #pragma unroll
                for (int j = 0; j < 8; j++) acc[i][j] += a[i] * bb[j];
        }
        __syncthreads();
    }

    float* Cb = C + (size_t)(by * 128 + ty * 8) * N + bx * 128 + tx * 8;
    #pragma unroll
    for (int i = 0; i < 8; i++) {
        float4 o0, o1;
        o0.x = acc[i][0]*alpha; o0.y = acc[i][1]*alpha; o0.z = acc[i][2]*alpha; o0.w = acc[i][3]*alpha;
        o1.x = acc[i][4]*alpha; o1.y = acc[i][5]*alpha; o1.z = acc[i][6]*alpha; o1.w = acc[i][7]*alpha;
        *(float4*)(Cb + (size_t)i * N)     = o0;
        *(float4*)(Cb + (size_t)i * N + 4) = o1;
    }
}

// ---------------- gelu + L2-rownorm (in place): y = gelu(a) * sqrt(cols)/||gelu(a)|| ----------------
__global__ void rownorm_kernel(float* __restrict__ a, int cols) {
    __shared__ float sh[32];
    int row = blockIdx.x;
    int tid = threadIdx.x;
    float* ar = a + (size_t)row * cols;
    float s = 0.0f;
    for (int c = tid * 4; c < cols; c += 1024) {
        float4 v = *(float4*)(ar + c);
        v.x = gelu_exact(v.x); v.y = gelu_exact(v.y);
        v.z = gelu_exact(v.z); v.w = gelu_exact(v.w);
        s += v.x*v.x + v.y*v.y + v.z*v.z + v.w*v.w;
        *(float4*)(ar + c) = v;
    }
    float tot = block_reduce_sum(s, sh);
    float sc = sqrtf((float)cols) * rsqrtf(tot);
    for (int c = tid * 4; c < cols; c += 1024) {
        float4 v = *(float4*)(ar + c);
        v.x *= sc; v.y *= sc; v.z *= sc; v.w *= sc;
        *(float4*)(ar + c) = v;
    }
}

// ---------------- RoPE on q,k (first 16 dims of each head) ----------------
__global__ void rope_kernel(float* __restrict__ q, float* __restrict__ k) {
    int idx = blockIdx.x * blockDim.x + threadIdx.x;   // (b*S+s)*NH + h
    if (idx >= T_ * NH_) return;
    int h  = idx & (NH_ - 1);
    int bs = idx >> 4;
    int s  = bs & (S_ - 1);
    float* qp = q + (size_t)bs * H_ + h * HD_;
    float* kp = k + (size_t)bs * H_ + h * HD_;
    float qv[ROT_], kv[ROT_];
    #pragma unroll
    for (int i = 0; i < ROT_; i++) { qv[i] = qp[i]; kv[i] = kp[i]; }
    #pragma unroll
    for (int i = 0; i < ROT_ / 2; i++) {
        double invf = pow(10000.0, -(double)(2 * i) / (double)ROT_);
        double ang = (double)s * invf;
        float c  = (float)cos(ang);
        float sn = (float)sin(ang);
        float q0 = qv[i], q1 = qv[i + 8];
        qv[i]     = q0 * c - q1 * sn;
        qv[i + 8] = q1 * c + q0 * sn;
        float k0 = kv[i], k1 = kv[i + 8];
        kv[i]     = k0 * c - k1 * sn;
        kv[i + 8] = k1 * c + k0 * sn;
    }
    #pragma unroll
    for (int i = 0; i < ROT_; i++) { qp[i] = qv[i]; kp[i] = kv[i]; }
}

// ---------------- fused causal attention with gelu-L2-norm ----------------
// gelu_l2_norm is gelu followed by a per-row scalar -> single pass:
// O = (sum_k gelu(qk/8)*V) * sqrt(S)/sqrt(sum_k gelu^2). Masked entries are exactly 0.
#define APAD 68
__global__ void __launch_bounds__(256) attn_kernel(
    const float* __restrict__ Q, const float* __restrict__ K,
    const float* __restrict__ V, float* __restrict__ O)
{
    extern __shared__ float sm[];
    float* Qs  = sm;                 // [64 dims][68] transposed: Qs[d][q]
    float* Ks  = Qs + 64 * APAD;     // [64 dims][68] transposed: Ks[d][k]
    float* Vs  = Ks + 64 * APAD;     // [64 k][68 dims] natural
    float* Ss  = Vs + 64 * APAD;     // [64 q][68 k]
    float* n2s = Ss + 64 * APAD;     // [64]

    const int qt  = blockIdx.x;      // 32 q-tiles of 64
    const int bh  = blockIdx.y;      // b*NH + h, 32
    const int b   = bh >> 4, h = bh & 15;
    const int tid = threadIdx.x, tx = tid & 15, ty = tid >> 4;
    const size_t base = (size_t)(b * S_) * H_ + h * HD_;

    // load Q tile, transposed
    #pragma unroll
    for (int it = 0; it < 4; it++) {
        int fl = tid + it * 256;          // [0,1024) float4 slots
        int r = fl >> 4, c4 = fl & 15;
        const float4 v = *(const float4*)(Q + base + (size_t)(qt * 64 + r) * H_ + c4 * 4);
        Qs[(c4*4+0)*APAD + r] = v.x;
        Qs[(c4*4+1)*APAD + r] = v.y;
        Qs[(c4*4+2)*APAD + r] = v.z;
        Qs[(c4*4+3)*APAD + r] = v.w;
    }

    float oacc[4][4];
    float n2p[4] = {0.f, 0.f, 0.f, 0.f};
    #pragma unroll
    for (int i = 0; i < 4; i++)
        #pragma unroll
        for (int j = 0; j < 4; j++) oacc[i][j] = 0.0f;

    for (int kt = 0; kt <= qt; kt++) {
        __syncthreads();   // previous Ss/Vs consumers done; also fences Q stores on first iter
        #pragma unroll
        for (int it = 0; it < 4; it++) {
            int fl = tid + it * 256;
            int r = fl >> 4, c4 = fl & 15;
            const float4 kvv = *(const float4*)(K + base + (size_t)(kt * 64 + r) * H_ + c4 * 4);
            Ks[(c4*4+0)*APAD + r] = kvv.x;
            Ks[(c4*4+1)*APAD + r] = kvv.y;
            Ks[(c4*4+2)*APAD + r] = kvv.z;
            Ks[(c4*4+3)*APAD + r] = kvv.w;
            const float4 vvv = *(const float4*)(V + base + (size_t)(kt * 64 + r) * H_ + c4 * 4);
            *(float4*)&Vs[r * APAD + c4 * 4] = vvv;
        }
        __syncthreads();

        // S = Q K^T (4x4 microtile per thread)
        float acc[4][4];
        #pragma unroll
        for (int i = 0; i < 4; i++)
            #pragma unroll
            for (int j = 0; j < 4; j++) acc[i][j] = 0.0f;
        #pragma unroll 8
        for (int t = 0; t < 64; t++) {
            float4 qv = *(const float4*)&Qs[t * APAD + ty * 4];
            float4 kv = *(const float4*)&Ks[t * APAD + tx * 4];
            float aq[4] = {qv.x, qv.y, qv.z, qv.w};
            float ak[4] = {kv.x, kv.y, kv.z, kv.w};
            #pragma unroll
            for (int i = 0; i < 4; i++)
                #pragma unroll
                for (int j = 0; j < 4; j++) acc[i][j] += aq[i] * ak[j];
        }
        // mask + gelu + n2 accumulation, store to Ss
        #pragma unroll
        for (int i = 0; i < 4; i++) {
            int qq = qt * 64 + ty * 4 + i;
            #pragma unroll
            for (int j = 0; j < 4; j++) {
                int kk = kt * 64 + tx * 4 + j;
                float g = 0.0f;
                if (kk <= qq) {
                    float sv = acc[i][j] * 0.125f;   // / sqrt(HD)
                    g = gelu_exact(sv);
                }
                n2p[i] += g * g;
                Ss[(ty * 4 + i) * APAD + tx * 4 + j] = g;
            }
        }
        __syncthreads();

        // O += Ss @ Vs
        #pragma unroll 8
        for (int t = 0; t < 64; t++) {
            float s0 = Ss[(ty * 4 + 0) * APAD + t];
            float s1 = Ss[(ty * 4 + 1) * APAD + t];
            float s2 = Ss[(ty * 4 + 2) * APAD + t];
            float s3 = Ss[(ty * 4 + 3) * APAD + t];
            float4 vv = *(const float4*)&Vs[t * APAD + tx * 4];
            float av[4] = {vv.x, vv.y, vv.z, vv.w};
            float as[4] = {s0, s1, s2, s3};
            #pragma unroll
            for (int i = 0; i < 4; i++)
                #pragma unroll
                for (int j = 0; j < 4; j++) oacc[i][j] += as[i] * av[j];
        }
    }

    // reduce n2 across tx-threads and scale
    __syncthreads();
    if (tid < 64) n2s[tid] = 0.0f;
    __syncthreads();
    #pragma unroll
    for (int i = 0; i < 4; i++) atomicAdd(&n2s[ty * 4 + i], n2p[i]);
    __syncthreads();

    const float sqS = 45.25483399593904f;   // sqrt(2048)
    #pragma unroll
    for (int i = 0; i < 4; i++) {
        float sc = sqS * rsqrtf(n2s[ty * 4 + i]);
        float4 o;
        o.x = oacc[i][0] * sc; o.y = oacc[i][1] * sc;
        o.z = oacc[i][2] * sc; o.w = oacc[i][3] * sc;
        *(float4*)(O + base + (size_t)(qt * 64 + ty * 4 + i) * H_ + tx * 4) = o;
    }
}

// ---------------- elementwise add ----------------
__global__ void add_kernel(const float* __restrict__ a, const float* __restrict__ b,
                           float* __restrict__ c, int n4) {
    int i = blockIdx.x * blockDim.x + threadIdx.x;
    if (i >= n4) return;
    float4 va = *(const float4*)(a + (size_t)i * 4);
    float4 vb = *(const float4*)(b + (size_t)i * 4);
    float4 o;
    o.x = va.x + vb.x; o.y = va.y + vb.y; o.z = va.z + vb.z; o.w = va.w + vb.w;
    *(float4*)(c + (size_t)i * 4) = o;
}

// ---------------- launch ----------------
extern "C" void kernel_launch(void* const* d_in, const int* in_sizes, int n_in,
                              void* d_out, int out_size) {
    const float* x        = (const float*)d_in[0];
    const float* ln1_w    = (const float*)d_in[1];
    const float* ln1_b    = (const float*)d_in[2];
    const float* ln2_w    = (const float*)d_in[3];
    const float* ln2_b    = (const float*)d_in[4];
    const float* q_key    = (const float*)d_in[5];
    const float* q_val    = (const float*)d_in[6];
    const float* k_key    = (const float*)d_in[7];
    const float* k_val    = (const float*)d_in[8];
    const float* v_key    = (const float*)d_in[9];
    const float* v_val    = (const float*)d_in[10];
    const float* proj_key = (const float*)d_in[11];
    const float* proj_val = (const float*)d_in[12];
    const float* ffn_key  = (const float*)d_in[13];
    const float* ffn_val  = (const float*)d_in[14];
    float* out = (float*)d_out;

    float *p_xn, *p_big, *p_q, *p_k, *p_v, *p_o, *p_x1, *p_tmp;
    cudaGetSymbolAddress((void**)&p_xn,  d_xn);
    cudaGetSymbolAddress((void**)&p_big, d_big);
    cudaGetSymbolAddress((void**)&p_q,   d_q);
    cudaGetSymbolAddress((void**)&p_k,   d_k);
    cudaGetSymbolAddress((void**)&p_v,   d_v);
    cudaGetSymbolAddress((void**)&p_o,   d_o);
    cudaGetSymbolAddress((void**)&p_x1,  d_x1);
    cudaGetSymbolAddress((void**)&p_tmp, d_tmp);

    const float sqrtH = 32.0f;   // sqrt(1024)
    dim3 g_small(H_ / 128, T_ / 128);       // (8, 32)
    dim3 g_ffn1(FFN_ / 128, T_ / 128);      // (32, 32)

    // x -> xn
    ln_kernel<<<T_, 256>>>(x, ln1_w, ln1_b, p_xn);

    // q / k / v pattention
    sgemm_kernel<true ><<<g_small, 256>>>(p_xn, q_key, p_big, T_, H_, H_, sqrtH);
    rownorm_kernel<<<T_, 256>>>(p_big, H_);
    sgemm_kernel<false><<<g_small, 256>>>(p_big, q_val, p_q, T_, H_, H_, 1.0f);

    sgemm_kernel<true ><<<g_small, 256>>>(p_xn, k_key, p_big, T_, H_, H_, sqrtH);
    rownorm_kernel<<<T_, 256>>>(p_big, H_);
    sgemm_kernel<false><<<g_small, 256>>>(p_big, k_val, p_k, T_, H_, H_, 1.0f);

    sgemm_kernel<true ><<<g_small, 256>>>(p_xn, v_key, p_big, T_, H_, H_, sqrtH);
    rownorm_kernel<<<T_, 256>>>(p_big, H_);
    sgemm_kernel<false><<<g_small, 256>>>(p_big, v_val, p_v, T_, H_, H_, 1.0f);

    // RoPE
    rope_kernel<<<(T_ * NH_) / 256, 256>>>(p_q, p_k);

    // attention
    {
        size_t smem = (4 * 64 * APAD + 64) * sizeof(float);   // ~70 KB
        cudaFuncSetAttribute(attn_kernel, cudaFuncAttributeMaxDynamicSharedMemorySize, (int)smem);
        dim3 grid(S_ / 64, B_ * NH_);   // (32, 32)
        attn_kernel<<<grid, 256, smem>>>(p_q, p_k, p_v, p_o);
    }

    // proj pattention + residual
    sgemm_kernel<true ><<<g_small, 256>>>(p_o, proj_key, p_big, T_, H_, H_, sqrtH);
    rownorm_kernel<<<T_, 256>>>(p_big, H_);
    sgemm_kernel<false><<<g_small, 256>>>(p_big, proj_val, p_tmp, T_, H_, H_, 1.0f);
    add_kernel<<<(T_ * H_ / 4 + 255) / 256, 256>>>(x, p_tmp, p_x1, T_ * H_ / 4);

    // ffn pattention + residual
    ln_kernel<<<T_, 256>>>(p_x1, ln2_w, ln2_b, p_xn);
    sgemm_kernel<true ><<<g_ffn1, 256>>>(p_xn, ffn_key, p_big, T_, FFN_, H_, sqrtH);
    rownorm_kernel<<<T_, 256>>>(p_big, FFN_);
    sgemm_kernel<false><<<g_small, 256>>>(p_big, ffn_val, p_tmp, T_, H_, FFN_, 1.0f);
    add_kernel<<<(T_ * H_ / 4 + 255) / 256, 256>>>(p_x1, p_tmp, out, T_ * H_ / 4);
}

// round 2
// speedup vs baseline: 2.5743x; 2.5743x over previous
#include <cuda_runtime.h>
#include <math.h>
#include <stdint.h>

// ---------------- problem constants ----------------
#define B_   2
#define S_   2048
#define H_   1024
#define NH_  16
#define HD_  64
#define T_   (B_*S_)      // 4096 tokens
#define FFN_ 4096
#define ROT_ 16

// ---------------- static scratch (no allocs allowed) ----------------
__device__ float d_xn [T_*H_];
__device__ float d_big[T_*FFN_];
__device__ float d_q  [T_*H_];
__device__ float d_k  [T_*H_];
__device__ float d_v  [T_*H_];
__device__ float d_o  [T_*H_];
__device__ float d_x1 [T_*H_];
__device__ float d_tmp[T_*H_];

// ---------------- helpers ----------------
__device__ __forceinline__ float gelu_exact(float x) {
    return 0.5f * x * (1.0f + erff(x * 0.7071067811865475f));
}

__device__ __forceinline__ uint32_t f2tf(float f) {
    uint32_t u;
    asm("cvt.rna.tf32.f32 %0, %1;" : "=r"(u) : "f"(f));
    return u;
}

__device__ __forceinline__ void mma_tf32(float* d, const uint32_t* a, const uint32_t* b) {
    asm volatile(
        "mma.sync.aligned.m16n8k8.row.col.f32.tf32.tf32.f32 "
        "{%0,%1,%2,%3}, {%4,%5,%6,%7}, {%8,%9}, {%0,%1,%2,%3};\n"
        : "+f"(d[0]), "+f"(d[1]), "+f"(d[2]), "+f"(d[3])
        : "r"(a[0]), "r"(a[1]), "r"(a[2]), "r"(a[3]), "r"(b[0]), "r"(b[1]));
}

__device__ __forceinline__ void cp_async16(uint32_t smem_addr, const void* gptr) {
    asm volatile("cp.async.cg.shared.global [%0], [%1], 16;\n" :: "r"(smem_addr), "l"(gptr));
}
#define CP_COMMIT() asm volatile("cp.async.commit_group;\n" ::: "memory")
#define CP_WAIT(n)  asm volatile("cp.async.wait_group %0;\n" :: "n"(n) : "memory")

__device__ __forceinline__ float block_reduce_sum(float v, float* sh) {
    int lane = threadIdx.x & 31, wid = threadIdx.x >> 5;
    #pragma unroll
    for (int o = 16; o > 0; o >>= 1) v += __shfl_down_sync(0xffffffffu, v, o);
    if (lane == 0) sh[wid] = v;
    __syncthreads();
    float r = (threadIdx.x < (blockDim.x >> 5)) ? sh[threadIdx.x] : 0.0f;
    if (wid == 0) {
        #pragma unroll
        for (int o = 4; o > 0; o >>= 1) r += __shfl_down_sync(0xffffffffu, r, o);
        if (lane == 0) sh[0] = r;
    }
    __syncthreads();
    r = sh[0];
    __syncthreads();
    return r;
}

// ---------------- LayerNorm ----------------
__global__ void ln_kernel(const float* __restrict__ x, const float* __restrict__ w,
                          const float* __restrict__ b, float* __restrict__ y) {
    __shared__ float sh[32];
    int row = blockIdx.x;
    int tid = threadIdx.x;
    const float4 v = *(const float4*)(x + (size_t)row * H_ + tid * 4);
    float s  = v.x + v.y + v.z + v.w;
    float sq = v.x*v.x + v.y*v.y + v.z*v.z + v.w*v.w;
    float S  = block_reduce_sum(s,  sh);
    float SQ = block_reduce_sum(sq, sh);
    float mu  = S * (1.0f / H_);
    float var = SQ * (1.0f / H_) - mu * mu;
    float inv = rsqrtf(var + 1e-5f);
    const float4 wv = *(const float4*)(w + tid * 4);
    const float4 bv = *(const float4*)(b + tid * 4);
    float4 o;
    o.x = (v.x - mu) * inv * wv.x + bv.x;
    o.y = (v.y - mu) * inv * wv.y + bv.y;
    o.z = (v.z - mu) * inv * wv.z + bv.z;
    o.w = (v.w - mu) * inv * wv.w + bv.w;
    *(float4*)(y + (size_t)row * H_ + tid * 4) = o;
}

// ---------------- TF32 tensor-core GEMM 128x128x32 ----------------
// C[M,N] = alpha * A[M,K] @ op(B).  TB: B is [N,K] (NT), else B is [K,N] (NN).
// Layouts: As[m][36] (bank (4m+k)%32 distinct). NT: Bs[n][36]. NN: Bs[k][132].
#define APAD_A 36
#define BPAD_NN 132

template <bool TB>
__global__ void __launch_bounds__(256, 2) mgemm_kernel(
    const float* __restrict__ A, const float* __restrict__ Bm, float* __restrict__ C,
    int M, int N, int K, float alpha)
{
    extern __shared__ float sh[];
    const int ASZ = 128 * APAD_A;                      // per-buffer A floats
    const int BSZ = TB ? (128 * APAD_A) : (32 * BPAD_NN);
    float* As = sh;                 // [2][ASZ]
    float* Bs = sh + 2 * ASZ;       // [2][BSZ]

    const int bx = blockIdx.x, by = blockIdx.y;
    const int tid = threadIdx.x;
    const int lane = tid & 31, wid = tid >> 5;
    const int wm = wid & 3, wn = wid >> 2;             // 4x2 warp grid; warp tile 32m x 64n
    const int lr = lane >> 2, lc = lane & 3;

    float acc[2][8][4];
    #pragma unroll
    for (int i = 0; i < 2; i++)
        #pragma unroll
        for (int j = 0; j < 8; j++)
            #pragma unroll
            for (int t = 0; t < 4; t++) acc[i][j][t] = 0.0f;

    const int iters = K >> 5;                          // K/32

    // tile loader via cp.async
    auto load_tile = [&](int t, int buf) {
        int k0 = t << 5;
        // A: 128 rows x 32 k = 1024 float4 slots
        #pragma unroll
        for (int it = 0; it < 4; it++) {
            int slot = tid + it * 256;
            int row = slot >> 3, k4 = slot & 7;
            const float* src = A + (size_t)(by * 128 + row) * K + k0 + k4 * 4;
            uint32_t dst = (uint32_t)__cvta_generic_to_shared(As + buf * ASZ + row * APAD_A + k4 * 4);
            cp_async16(dst, src);
        }
        if (TB) {
            #pragma unroll
            for (int it = 0; it < 4; it++) {
                int slot = tid + it * 256;
                int row = slot >> 3, k4 = slot & 7;
                const float* src = Bm + (size_t)(bx * 128 + row) * K + k0 + k4 * 4;
                uint32_t dst = (uint32_t)__cvta_generic_to_shared(Bs + buf * BSZ + row * APAD_A + k4 * 4);
                cp_async16(dst, src);
            }
        } else {
            #pragma unroll
            for (int it = 0; it < 4; it++) {
                int slot = tid + it * 256;
                int kk = slot >> 5, n4 = slot & 31;
                const float* src = Bm + (size_t)(k0 + kk) * N + bx * 128 + n4 * 4;
                uint32_t dst = (uint32_t)__cvta_generic_to_shared(Bs + buf * BSZ + kk * BPAD_NN + n4 * 4);
                cp_async16(dst, src);
            }
        }
    };

    load_tile(0, 0);
    CP_COMMIT();

    int buf = 0;
    for (int t = 0; t < iters; t++) {
        if (t + 1 < iters) {
            load_tile(t + 1, buf ^ 1);
            CP_COMMIT();
            CP_WAIT(1);
        } else {
            CP_WAIT(0);
        }
        __syncthreads();

        const float* Ab = As + buf * ASZ;
        const float* Bb = Bs + buf * BSZ;
        #pragma unroll
        for (int ks = 0; ks < 4; ks++) {
            int kb = ks * 8;
            uint32_t afr[2][4];
            #pragma unroll
            for (int mt = 0; mt < 2; mt++) {
                const float* ap = Ab + (wm * 32 + mt * 16 + lr) * APAD_A + kb + lc;
                afr[mt][0] = f2tf(ap[0]);
                afr[mt][1] = f2tf(ap[8 * APAD_A]);
                afr[mt][2] = f2tf(ap[4]);
                afr[mt][3] = f2tf(ap[8 * APAD_A + 4]);
            }
            #pragma unroll
            for (int nt = 0; nt < 8; nt++) {
                uint32_t bfr[2];
                if (TB) {
                    const float* bp = Bb + (wn * 64 + nt * 8 + lr) * APAD_A + kb + lc;
                    bfr[0] = f2tf(bp[0]);
                    bfr[1] = f2tf(bp[4]);
                } else {
                    const float* bp = Bb + (kb + lc) * BPAD_NN + wn * 64 + nt * 8 + lr;
                    bfr[0] = f2tf(bp[0]);
                    bfr[1] = f2tf(bp[4 * BPAD_NN]);
                }
                mma_tf32(acc[0][nt], afr[0], bfr);
                mma_tf32(acc[1][nt], afr[1], bfr);
            }
        }
        buf ^= 1;
        __syncthreads();
    }

    // epilogue
    #pragma unroll
    for (int mt = 0; mt < 2; mt++) {
        int r0 = by * 128 + wm * 32 + mt * 16 + lr;
        #pragma unroll
        for (int nt = 0; nt < 8; nt++) {
            int c = bx * 128 + wn * 64 + nt * 8 + 2 * lc;
            float2 lo = {acc[mt][nt][0] * alpha, acc[mt][nt][1] * alpha};
            float2 hi = {acc[mt][nt][2] * alpha, acc[mt][nt][3] * alpha};
            *(float2*)(C + (size_t)r0 * N + c)       = lo;
            *(float2*)(C + (size_t)(r0 + 8) * N + c) = hi;
        }
    }
}

// ---------------- gelu + L2-rownorm (in place) ----------------
__global__ void rownorm_kernel(float* __restrict__ a, int cols) {
    __shared__ float sh[32];
    int row = blockIdx.x;
    int tid = threadIdx.x;
    float* ar = a + (size_t)row * cols;
    float s = 0.0f;
    for (int c = tid * 4; c < cols; c += 1024) {
        float4 v = *(float4*)(ar + c);
        v.x = gelu_exact(v.x); v.y = gelu_exact(v.y);
        v.z = gelu_exact(v.z); v.w = gelu_exact(v.w);
        s += v.x*v.x + v.y*v.y + v.z*v.z + v.w*v.w;
        *(float4*)(ar + c) = v;
    }
    float tot = block_reduce_sum(s, sh);
    float sc = sqrtf((float)cols) * rsqrtf(tot);
    for (int c = tid * 4; c < cols; c += 1024) {
        float4 v = *(float4*)(ar + c);
        v.x *= sc; v.y *= sc; v.z *= sc; v.w *= sc;
        *(float4*)(ar + c) = v;
    }
}

// ---------------- RoPE ----------------
__global__ void rope_kernel(float* __restrict__ q, float* __restrict__ k) {
    int idx = blockIdx.x * blockDim.x + threadIdx.x;
    if (idx >= T_ * NH_) return;
    int h  = idx & (NH_ - 1);
    int bs = idx >> 4;
    int s  = bs & (S_ - 1);
    float* qp = q + (size_t)bs * H_ + h * HD_;
    float* kp = k + (size_t)bs * H_ + h * HD_;
    float qv[ROT_], kv[ROT_];
    #pragma unroll
    for (int i = 0; i < ROT_; i++) { qv[i] = qp[i]; kv[i] = kp[i]; }
    #pragma unroll
    for (int i = 0; i < ROT_ / 2; i++) {
        double invf = pow(10000.0, -(double)(2 * i) / (double)ROT_);
        double ang = (double)s * invf;
        float c  = (float)cos(ang);
        float sn = (float)sin(ang);
        float q0 = qv[i], q1 = qv[i + 8];
        qv[i]     = q0 * c - q1 * sn;
        qv[i + 8] = q1 * c + q0 * sn;
        float k0 = kv[i], k1 = kv[i + 8];
        kv[i]     = k0 * c - k1 * sn;
        kv[i + 8] = k1 * c + k0 * sn;
    }
    #pragma unroll
    for (int i = 0; i < ROT_; i++) { qp[i] = qv[i]; kp[i] = kv[i]; }
}

// ---------------- fused causal attention (tf32 mma, single pass) ----------------
// O = (sum_k gelu(qk/8)*V) * sqrt(S)/sqrt(sum_k gelu^2); masked entries exactly 0.
#define ATPAD 68
__global__ void __launch_bounds__(128, 2) attn_kernel(
    const float* __restrict__ Q, const float* __restrict__ K,
    const float* __restrict__ V, float* __restrict__ O)
{
    extern __shared__ float sm[];
    float* Qs = sm;                    // [64][68]  q x d
    float* Ks = Qs + 64 * ATPAD;       // [64][68]  tok x d
    float* Vs = Ks + 64 * ATPAD;       // [64][68]  tok x d
    float* Ss = Vs + 64 * ATPAD;       // [64][68]  q x tok

    const int qt  = blockIdx.x;
    const int bh  = blockIdx.y;
    const int b   = bh >> 4, h = bh & 15;
    const int tid = threadIdx.x;
    const int lane = tid & 31, w = tid >> 5;    // 4 warps, 16 q-rows each
    const int lr = lane >> 2, lc = lane & 3;
    const size_t base = (size_t)(b * S_) * H_ + h * HD_;

    // load Q tile [64 q][64 d]
    #pragma unroll
    for (int it = 0; it < 8; it++) {
        int slot = tid + it * 128;
        int row = slot >> 4, c4 = slot & 15;
        float4 v = *(const float4*)(Q + base + (size_t)(qt * 64 + row) * H_ + c4 * 4);
        *(float4*)(Qs + row * ATPAD + c4 * 4) = v;
    }

    float oacc[8][4];
    #pragma unroll
    for (int i = 0; i < 8; i++)
        #pragma unroll
        for (int j = 0; j < 4; j++) oacc[i][j] = 0.0f;
    float n2lo = 0.0f, n2hi = 0.0f;

    for (int kt = 0; kt <= qt; kt++) {
        __syncthreads();   // prev Ks/Vs consumers done (also fences Qs on iter 0)
        #pragma unroll
        for (int it = 0; it < 8; it++) {
            int slot = tid + it * 128;
            int row = slot >> 4, c4 = slot & 15;
            float4 kv = *(const float4*)(K + base + (size_t)(kt * 64 + row) * H_ + c4 * 4);
            *(float4*)(Ks + row * ATPAD + c4 * 4) = kv;
            float4 vv = *(const float4*)(V + base + (size_t)(kt * 64 + row) * H_ + c4 * 4);
            *(float4*)(Vs + row * ATPAD + c4 * 4) = vv;
        }
        __syncthreads();

        // S = Q K^T : per warp 16q x 64tok
        float sacc[8][4];
        #pragma unroll
        for (int i = 0; i < 8; i++)
            #pragma unroll
            for (int j = 0; j < 4; j++) sacc[i][j] = 0.0f;
        #pragma unroll
        for (int ks = 0; ks < 8; ks++) {
            int kb = ks * 8;
            const float* ap = Qs + (w * 16 + lr) * ATPAD + kb + lc;
            uint32_t a[4];
            a[0] = f2tf(ap[0]);
            a[1] = f2tf(ap[8 * ATPAD]);
            a[2] = f2tf(ap[4]);
            a[3] = f2tf(ap[8 * ATPAD + 4]);
            #pragma unroll
            for (int nt = 0; nt < 8; nt++) {
                const float* bp = Ks + (nt * 8 + lr) * ATPAD + kb + lc;
                uint32_t bfr[2];
                bfr[0] = f2tf(bp[0]);
                bfr[1] = f2tf(bp[4]);
                mma_tf32(sacc[nt], a, bfr);
            }
        }

        // mask + gelu + n2, write to Ss
        int q0 = qt * 64 + w * 16 + lr;
        #pragma unroll
        for (int nt = 0; nt < 8; nt++) {
            int k0c = kt * 64 + nt * 8 + 2 * lc;
            float g0 = (k0c     <= q0) ? gelu_exact(sacc[nt][0] * 0.125f) : 0.0f;
            float g1 = (k0c + 1 <= q0) ? gelu_exact(sacc[nt][1] * 0.125f) : 0.0f;
            float g2 = (k0c     <= q0 + 8) ? gelu_exact(sacc[nt][2] * 0.125f) : 0.0f;
            float g3 = (k0c + 1 <= q0 + 8) ? gelu_exact(sacc[nt][3] * 0.125f) : 0.0f;
            n2lo += g0 * g0 + g1 * g1;
            n2hi += g2 * g2 + g3 * g3;
            float2 lo = {g0, g1}, hi = {g2, g3};
            *(float2*)(Ss + (w * 16 + lr) * ATPAD + nt * 8 + 2 * lc)       = lo;
            *(float2*)(Ss + (w * 16 + lr + 8) * ATPAD + nt * 8 + 2 * lc)   = hi;
        }
        __syncwarp();   // Ss rows are warp-private; only warp-level visibility needed

        // O += Ss @ Vs
        #pragma unroll
        for (int ks = 0; ks < 8; ks++) {
            int kb = ks * 8;
            const float* ap = Ss + (w * 16 + lr) * ATPAD + kb + lc;
            uint32_t a[4];
            a[0] = f2tf(ap[0]);
            a[1] = f2tf(ap[8 * ATPAD]);
            a[2] = f2tf(ap[4]);
            a[3] = f2tf(ap[8 * ATPAD + 4]);
            #pragma unroll
            for (int nt = 0; nt < 8; nt++) {
                const float* bp = Vs + (kb + lc) * ATPAD + nt * 8 + lr;
                uint32_t bfr[2];
                bfr[0] = f2tf(bp[0]);
                bfr[1] = f2tf(bp[4 * ATPAD]);
                mma_tf32(oacc[nt], a, bfr);
            }
        }
    }

    // reduce n2 across the 4 lanes sharing each row
    n2lo += __shfl_xor_sync(0xffffffffu, n2lo, 1);
    n2lo += __shfl_xor_sync(0xffffffffu, n2lo, 2);
    n2hi += __shfl_xor_sync(0xffffffffu, n2hi, 1);
    n2hi += __shfl_xor_sync(0xffffffffu, n2hi, 2);

    const float sqS = 45.25483399593904f;   // sqrt(2048)
    float sclo = sqS * rsqrtf(n2lo);
    float schi = sqS * rsqrtf(n2hi);

    int r0 = qt * 64 + w * 16 + lr;
    #pragma unroll
    for (int nt = 0; nt < 8; nt++) {
        int c = nt * 8 + 2 * lc;
        float2 lo = {oacc[nt][0] * sclo, oacc[nt][1] * sclo};
        float2 hi = {oacc[nt][2] * schi, oacc[nt][3] * schi};
        *(float2*)(O + base + (size_t)r0 * H_ + c)       = lo;
        *(float2*)(O + base + (size_t)(r0 + 8) * H_ + c) = hi;
    }
}

// ---------------- elementwise add ----------------
__global__ void add_kernel(const float* __restrict__ a, const float* __restrict__ b,
                           float* __restrict__ c, int n4) {
    int i = blockIdx.x * blockDim.x + threadIdx.x;
    if (i >= n4) return;
    float4 va = *(const float4*)(a + (size_t)i * 4);
    float4 vb = *(const float4*)(b + (size_t)i * 4);
    float4 o;
    o.x = va.x + vb.x; o.y = va.y + vb.y; o.z = va.z + vb.z; o.w = va.w + vb.w;
    *(float4*)(c + (size_t)i * 4) = o;
}

// ---------------- launch ----------------
extern "C" void kernel_launch(void* const* d_in, const int* in_sizes, int n_in,
                              void* d_out, int out_size) {
    const float* x        = (const float*)d_in[0];
    const float* ln1_w    = (const float*)d_in[1];
    const float* ln1_b    = (const float*)d_in[2];
    const float* ln2_w    = (const float*)d_in[3];
    const float* ln2_b    = (const float*)d_in[4];
    const float* q_key    = (const float*)d_in[5];
    const float* q_val    = (const float*)d_in[6];
    const float* k_key    = (const float*)d_in[7];
    const float* k_val    = (const float*)d_in[8];
    const float* v_key    = (const float*)d_in[9];
    const float* v_val    = (const float*)d_in[10];
    const float* proj_key = (const float*)d_in[11];
    const float* proj_val = (const float*)d_in[12];
    const float* ffn_key  = (const float*)d_in[13];
    const float* ffn_val  = (const float*)d_in[14];
    float* out = (float*)d_out;

    float *p_xn, *p_big, *p_q, *p_k, *p_v, *p_o, *p_x1, *p_tmp;
    cudaGetSymbolAddress((void**)&p_xn,  d_xn);
    cudaGetSymbolAddress((void**)&p_big, d_big);
    cudaGetSymbolAddress((void**)&p_q,   d_q);
    cudaGetSymbolAddress((void**)&p_k,   d_k);
    cudaGetSymbolAddress((void**)&p_v,   d_v);
    cudaGetSymbolAddress((void**)&p_o,   d_o);
    cudaGetSymbolAddress((void**)&p_x1,  d_x1);
    cudaGetSymbolAddress((void**)&p_tmp, d_tmp);

    const float sqrtH = 32.0f;   // sqrt(1024)
    dim3 g_small(H_ / 128, T_ / 128);       // (8, 32)
    dim3 g_ffn1(FFN_ / 128, T_ / 128);      // (32, 32)

    const int smem_nt = 2 * (128 * APAD_A) * 4 * 2;                 // 73728
    const int smem_nn = (2 * 128 * APAD_A + 2 * 32 * BPAD_NN) * 4;  // 70656
    cudaFuncSetAttribute(mgemm_kernel<true>,  cudaFuncAttributeMaxDynamicSharedMemorySize, smem_nt);
    cudaFuncSetAttribute(mgemm_kernel<false>, cudaFuncAttributeMaxDynamicSharedMemorySize, smem_nn);

    // x -> xn
    ln_kernel<<<T_, 256>>>(x, ln1_w, ln1_b, p_xn);

    // q / k / v pattention
    mgemm_kernel<true ><<<g_small, 256, smem_nt>>>(p_xn, q_key, p_big, T_, H_, H_, sqrtH);
    rownorm_kernel<<<T_, 256>>>(p_big, H_);
    mgemm_kernel<false><<<g_small, 256, smem_nn>>>(p_big, q_val, p_q, T_, H_, H_, 1.0f);

    mgemm_kernel<true ><<<g_small, 256, smem_nt>>>(p_xn, k_key, p_big, T_, H_, H_, sqrtH);
    rownorm_kernel<<<T_, 256>>>(p_big, H_);
    mgemm_kernel<false><<<g_small, 256, smem_nn>>>(p_big, k_val, p_k, T_, H_, H_, 1.0f);

    mgemm_kernel<true ><<<g_small, 256, smem_nt>>>(p_xn, v_key, p_big, T_, H_, H_, sqrtH);
    rownorm_kernel<<<T_, 256>>>(p_big, H_);
    mgemm_kernel<false><<<g_small, 256, smem_nn>>>(p_big, v_val, p_v, T_, H_, H_, 1.0f);

    // RoPE
    rope_kernel<<<(T_ * NH_) / 256, 256>>>(p_q, p_k);

    // attention
    {
        int smem = 4 * 64 * ATPAD * sizeof(float);   // ~69.6 KB
        cudaFuncSetAttribute(attn_kernel, cudaFuncAttributeMaxDynamicSharedMemorySize, smem);
        dim3 grid(S_ / 64, B_ * NH_);   // (32, 32)
        attn_kernel<<<grid, 128, smem>>>(p_q, p_k, p_v, p_o);
    }

    // proj pattention + residual
    mgemm_kernel<true ><<<g_small, 256, smem_nt>>>(p_o, proj_key, p_big, T_, H_, H_, sqrtH);
    rownorm_kernel<<<T_, 256>>>(p_big, H_);
    mgemm_kernel<false><<<g_small, 256, smem_nn>>>(p_big, proj_val, p_tmp, T_, H_, H_, 1.0f);
    add_kernel<<<(T_ * H_ / 4 + 255) / 256, 256>>>(x, p_tmp, p_x1, T_ * H_ / 4);

    // ffn pattention + residual
    ln_kernel<<<T_, 256>>>(p_x1, ln2_w, ln2_b, p_xn);
    mgemm_kernel<true ><<<g_ffn1, 256, smem_nt>>>(p_xn, ffn_key, p_big, T_, FFN_, H_, sqrtH);
    rownorm_kernel<<<T_, 256>>>(p_big, FFN_);
    mgemm_kernel<false><<<g_small, 256, smem_nn>>>(p_big, ffn_val, p_tmp, T_, H_, FFN_, 1.0f);
    add_kernel<<<(T_ * H_ / 4 + 255) / 256, 256>>>(p_x1, p_tmp, out, T_ * H_ / 4);
}